// round 1
// baseline (speedup 1.0000x reference)
#include <cuda_runtime.h>
#include <math.h>

// BboxDetectionHead: decode + threshold + exact greedy NMS (lazy sorted-order form)
//
// Scratch in __device__ globals (no allocation in kernel_launch).
#define N_MAX 196608            // 2048 * 96  (actual N = 196416)
#define TILE  96
#define TMAX  2048
#define MAXDET 100

__device__ float              g_scores[N_MAX];
__device__ float4             g_boxes[N_MAX];
__device__ int                g_cls[N_MAX];
__device__ unsigned long long g_tileKey[TMAX];

// Monotone order-preserving float32 -> uint32 (works for -inf too).
__device__ __forceinline__ unsigned ordf(float f) {
    unsigned u = __float_as_uint(f);
    return (u & 0x80000000u) ? ~u : (u | 0x80000000u);
}
__device__ __forceinline__ float unordf(unsigned u) {
    return __uint_as_float((u & 0x80000000u) ? (u ^ 0x80000000u) : ~u);
}

// Robust scalar read: harness may pass img_h/img_w as int32/float32/float64/int64.
__device__ __forceinline__ float read_dim(const void* p) {
    int iv = *(const int*)p;
    if (iv >= 1 && iv <= (1 << 20)) return (float)iv;
    float fv = *(const float*)p;
    if (fv >= 1.0f && fv <= 1048576.0f) return fv;
    double dv = *(const double*)p;
    if (dv >= 1.0 && dv <= 1048576.0) return (float)dv;
    long long lv = *(const long long*)p;
    return (float)lv;
}

__device__ __forceinline__ bool iou_gt_half(float4 A, float4 B) {
    float x1 = fmaxf(A.x, B.x), y1 = fmaxf(A.y, B.y);
    float x2 = fminf(A.z, B.z), y2 = fminf(A.w, B.w);
    float inter = fmaxf(x2 - x1, 0.0f) * fmaxf(y2 - y1, 0.0f);
    float a1 = (A.z - A.x) * (A.w - A.y);
    float a2 = (B.z - B.x) * (B.w - B.y);
    float iou = inter / (a1 + a2 - inter + 1e-8f);
    return iou > 0.5f;
}

// ---------------------------------------------------------------------------
// Kernel 1: one warp per anchor. Class max+argmax (first-index ties), decode,
// clip, threshold. Coalesced classification reads.
// ---------------------------------------------------------------------------
__global__ void decode_kernel(const float* __restrict__ cls,
                              const float* __restrict__ reg,
                              const float* __restrict__ anc,
                              const void* ph, const void* pw,
                              int N, int C) {
    int warp = (blockIdx.x * blockDim.x + threadIdx.x) >> 5;
    int lane = threadIdx.x & 31;
    if (warp >= N) return;

    const float* row = cls + (long long)warp * C;
    float best = -INFINITY;
    int   bidx = 0x7fffffff;
    for (int j = lane; j < C; j += 32) {
        float v = row[j];
        if (v > best) { best = v; bidx = j; }   // in-lane j increasing -> first occurrence kept
    }
    #pragma unroll
    for (int off = 16; off; off >>= 1) {
        float ov = __shfl_down_sync(0xffffffffu, best, off);
        int   oi = __shfl_down_sync(0xffffffffu, bidx, off);
        if (ov > best || (ov == best && oi < bidx)) { best = ov; bidx = oi; }
    }

    if (lane == 0) {
        float imw = read_dim(pw);
        float imh = read_dim(ph);
        float4 a = ((const float4*)anc)[warp];
        float4 r = ((const float4*)reg)[warp];
        float wa  = a.z - a.x;
        float ha  = a.w - a.y;
        float cxa = a.x + 0.5f * wa;
        float cya = a.y + 0.5f * ha;
        float cx  = cxa + r.x * 0.1f * wa;
        float cy  = cya + r.y * 0.1f * ha;
        float w   = expf(r.z * 0.2f) * wa;
        float h   = expf(r.w * 0.2f) * ha;
        float4 b;
        b.x = fminf(fmaxf(cx - 0.5f * w, 0.0f), imw);
        b.y = fminf(fmaxf(cy - 0.5f * h, 0.0f), imh);
        b.z = fminf(fmaxf(cx + 0.5f * w, 0.0f), imw);
        b.w = fminf(fmaxf(cy + 0.5f * h, 0.0f), imh);
        g_boxes[warp]  = b;
        g_cls[warp]    = bidx;
        g_scores[warp] = (best > 0.01f) ? best : -INFINITY;
    }
}

// ---------------------------------------------------------------------------
// Kernel 2: one warp per tile of 96 anchors -> 64-bit key (score, ~idx).
// Max of keys = max score, ties broken toward LOWEST global index.
// ---------------------------------------------------------------------------
__global__ void tilemax_kernel(int N, int T) {
    int t    = (blockIdx.x * blockDim.x + threadIdx.x) >> 5;
    int lane = threadIdx.x & 31;
    if (t >= T) return;
    unsigned long long key = 0ull;
    for (int k = lane; k < TILE; k += 32) {
        int i = t * TILE + k;
        float s = (i < N) ? g_scores[i] : -INFINITY;
        unsigned long long kk =
            ((unsigned long long)ordf(s) << 32) | (unsigned)(~i);
        key = (kk > key) ? kk : key;
    }
    #pragma unroll
    for (int off = 16; off; off >>= 1) {
        unsigned long long o = __shfl_down_sync(0xffffffffu, key, off);
        key = (o > key) ? o : key;
    }
    if (lane == 0) g_tileKey[t] = key;
}

// ---------------------------------------------------------------------------
// Kernel 3: single block. Lazy sorted-order NMS (exact equivalent of the
// reference's 100-round greedy scan).
// Output layout (float32, return order, flattened):
//   [0,100)    nms_scores
//   [100,200)  nms_class   (-1 invalid)
//   [200,600)  nms_boxes   (row-major [100,4])
//   [600,700)  keep        (1.0 / 0.0)
// ---------------------------------------------------------------------------
__global__ void nms_kernel(float* __restrict__ out, int N, int T) {
    __shared__ unsigned long long sKey[TMAX];
    __shared__ float4 sSel[MAXDET];
    __shared__ float4 sBx;
    __shared__ int    sSup;
    __shared__ int    sNsel;
    __shared__ unsigned long long sWarp[8];
    __shared__ unsigned long long sTileP[3];

    int tid  = threadIdx.x;
    int wid  = tid >> 5;
    int lane = tid & 31;

    for (int k = tid; k < TMAX; k += 256)
        sKey[k] = (k < T) ? g_tileKey[k] : 0ull;
    if (tid == 0) sNsel = 0;
    __syncthreads();

    int nsel = 0;
    while (nsel < MAXDET) {
        // ---- block argmax over tile keys ----
        unsigned long long best = 0ull;
        #pragma unroll
        for (int k = 0; k < TMAX / 256; k++) {
            unsigned long long v = sKey[tid + k * 256];
            best = (v > best) ? v : best;
        }
        #pragma unroll
        for (int off = 16; off; off >>= 1) {
            unsigned long long o = __shfl_down_sync(0xffffffffu, best, off);
            best = (o > best) ? o : best;
        }
        if (lane == 0) sWarp[wid] = best;
        __syncthreads();
        if (tid < 32) {
            unsigned long long v = (tid < 8) ? sWarp[tid] : 0ull;
            #pragma unroll
            for (int off = 4; off; off >>= 1) {
                unsigned long long o = __shfl_down_sync(0xffffffffu, v, off);
                v = (o > v) ? o : v;
            }
            if (tid == 0) sWarp[0] = v;
        }
        __syncthreads();

        unsigned long long win = sWarp[0];
        unsigned hi = (unsigned)(win >> 32);
        if (hi <= 0x007FFFFFu) break;        // best remaining is -inf -> done
        int   i   = (int)(~(unsigned)(win & 0xffffffffu));
        float val = unordf(hi);

        if (tid == 0) {
            g_scores[i] = -INFINITY;          // pop candidate
            sBx  = g_boxes[i];
            sSup = 0;
        }
        __syncthreads();

        int t = i / TILE;
        // ---- rescan popped tile (threads 0..95) ----
        if (tid < TILE) {
            int ii = t * TILE + tid;
            float s = (ii < N) ? g_scores[ii] : -INFINITY;
            unsigned long long kk =
                ((unsigned long long)ordf(s) << 32) | (unsigned)(~ii);
            #pragma unroll
            for (int off = 16; off; off >>= 1) {
                unsigned long long o = __shfl_down_sync(0xffffffffu, kk, off);
                kk = (o > kk) ? o : kk;
            }
            if (lane == 0) sTileP[wid] = kk;
        }
        // ---- concurrent IoU vs previously selected (threads 128..227) ----
        if (tid >= 128 && tid < 128 + nsel) {
            if (iou_gt_half(sSel[tid - 128], sBx)) sSup = 1;
        }
        __syncthreads();

        if (tid == 0) {
            unsigned long long kk = sTileP[0];
            if (sTileP[1] > kk) kk = sTileP[1];
            if (sTileP[2] > kk) kk = sTileP[2];
            sKey[t] = kk;
            if (!sSup) {
                float4 b = sBx;
                out[nsel]                 = val;
                out[100 + nsel]           = (float)g_cls[i];
                out[200 + 4 * nsel + 0]   = b.x;
                out[200 + 4 * nsel + 1]   = b.y;
                out[200 + 4 * nsel + 2]   = b.z;
                out[200 + 4 * nsel + 3]   = b.w;
                out[600 + nsel]           = 1.0f;
                sSel[nsel] = b;
                sNsel = nsel + 1;
            }
        }
        __syncthreads();
        nsel = sNsel;
    }

    // fill unused rows with reference defaults
    for (int k = nsel + tid; k < MAXDET; k += 256) {
        out[k]               = 0.0f;
        out[100 + k]         = -1.0f;
        out[200 + 4 * k + 0] = 0.0f;
        out[200 + 4 * k + 1] = 0.0f;
        out[200 + 4 * k + 2] = 0.0f;
        out[200 + 4 * k + 3] = 0.0f;
        out[600 + k]         = 0.0f;
    }
}

extern "C" void kernel_launch(void* const* d_in, const int* in_sizes, int n_in,
                              void* d_out, int out_size) {
    const float* cls = (const float*)d_in[0];
    const float* reg = (const float*)d_in[1];
    const float* anc = (const float*)d_in[2];
    const void*  ph  = d_in[3];
    const void*  pw  = d_in[4];

    int N = in_sizes[2] / 4;          // anchors [1, N, 4]
    int C = in_sizes[0] / N;          // classification [1, N, C]
    int T = (N + TILE - 1) / TILE;

    int blocksA = (N + 7) / 8;        // 8 warps (256 threads) per block, warp/anchor
    decode_kernel<<<blocksA, 256>>>(cls, reg, anc, ph, pw, N, C);

    int blocksT = (T + 7) / 8;        // warp per tile
    tilemax_kernel<<<blocksT, 256>>>(N, T);

    nms_kernel<<<1, 256>>>((float*)d_out, N, T);
}